// round 3
// baseline (speedup 1.0000x reference)
#include <cuda_runtime.h>

#define B_ 8192
#define D_ 3072
#define C_ 512
#define E_ 8
#define TM 128
#define TN 128
#define TK 16
#define NTHREADS 256
#define MT_MAX (B_/TM + E_)       /* 72 */
#define B_PAD (MT_MAX*TM)         /* 9216 */
#define NT_DEC (D_/TN)            /* 24 */
#define NT_ENC (C_/TN)            /* 4  */

__device__ int   g_counts[E_];
__device__ int   g_seg[E_+1];
__device__ int   g_perm[B_PAD];
__device__ int   g_is64;
__device__ float g_code[(size_t)B_PAD * C_];   // ~18.9 MB scratch (padded-position layout)
__device__ float g_partial[MT_MAX * NT_DEC];   // per-tile loss partials

// ---------------------------------------------------------------------------
// init: perm = -1, is64 flag default
// ---------------------------------------------------------------------------
__global__ void k_init() {
    int t = blockIdx.x * blockDim.x + threadIdx.x;
    if (t < B_PAD) g_perm[t] = -1;
    if (t == 0) g_is64 = 1;
}

// Detect label dtype: if interpreting the buffer as int64 yields any value
// outside [0, E), it must be int32. Reading B_/2 int64 == B_ int32 bytes, so
// this never overruns the smaller possible buffer.
__global__ void k_detect(const long long* lab) {
    int t = blockIdx.x * blockDim.x + threadIdx.x;
    if (t < B_/2) {
        long long v = lab[t];
        if (v < 0 || v >= E_) atomicExch(&g_is64, 0);
    }
}

__device__ __forceinline__ int get_label(const void* lab, int b) {
    int e;
    if (g_is64) e = (int)((const long long*)lab)[b];
    else        e = ((const int*)lab)[b];
    if (e < 0) e = 0;
    if (e >= E_) e = E_ - 1;
    return e;
}

// ---------------------------------------------------------------------------
// Deterministic routing: counts, TM-aligned segment starts, stable permutation.
// One block, 256 threads; each thread owns 32 consecutive rows.
// ---------------------------------------------------------------------------
__global__ void k_route(const void* lab) {
    __shared__ int cnt[NTHREADS][E_];
    int t = threadIdx.x;
    #pragma unroll
    for (int e = 0; e < E_; e++) cnt[t][e] = 0;
    int b0 = t * 32;
    #pragma unroll
    for (int i = 0; i < 32; i++) {
        int e = get_label(lab, b0 + i);
        cnt[t][e]++;
    }
    __syncthreads();
    // per-expert exclusive prefix over thread chunks (thread e handles expert e)
    if (t < E_) {
        int s = 0;
        for (int q = 0; q < NTHREADS; q++) { int c = cnt[q][t]; cnt[q][t] = s; s += c; }
        g_counts[t] = s;
    }
    __syncthreads();
    if (t == 0) {
        int s = 0;
        for (int e = 0; e < E_; e++) { g_seg[e] = s; s += ((g_counts[e] + TM - 1) / TM) * TM; }
        g_seg[E_] = s;
    }
    __syncthreads();
    int base[E_];
    #pragma unroll
    for (int e = 0; e < E_; e++) base[e] = g_seg[e] + cnt[t][e];
    #pragma unroll
    for (int i = 0; i < 32; i++) {
        int e = get_label(lab, b0 + i);
        g_perm[base[e]++] = b0 + i;
    }
}

// ---------------------------------------------------------------------------
// Encoder GEMM: code[pos, 0:512] = relu(img[perm[pos]] @ W_enc[e].T + b_enc[e])
// 128x128 tile, K=3072, 256 threads, 8x8 micro-tile.
// ---------------------------------------------------------------------------
__global__ void __launch_bounds__(NTHREADS) k_enc(
    const float* __restrict__ img, const float* __restrict__ Wenc,
    const float* __restrict__ benc)
{
    __shared__ float As[TK][TM];
    __shared__ float Bs[TK][TN];
    __shared__ int rows[TM];
    int m0 = blockIdx.x * TM;
    int total = g_seg[E_];
    if (m0 >= total) return;
    int e = 0;
    while (m0 >= g_seg[e + 1]) e++;
    int n0 = blockIdx.y * TN;
    const float* W = Wenc + (size_t)e * C_ * D_;
    int tid = threadIdx.x;
    if (tid < TM) rows[tid] = g_perm[m0 + tid];
    __syncthreads();
    int tx = tid & 15, ty = tid >> 4;
    float acc[8][8];
    #pragma unroll
    for (int i = 0; i < 8; i++)
        #pragma unroll
        for (int j = 0; j < 8; j++) acc[i][j] = 0.f;

    for (int kt = 0; kt < D_; kt += TK) {
        #pragma unroll
        for (int l = 0; l < 2; l++) {
            int f = tid + l * NTHREADS;
            int r = f >> 2, cg = f & 3;
            int row = rows[r];
            float4 v = make_float4(0.f, 0.f, 0.f, 0.f);
            if (row >= 0)
                v = *(const float4*)(img + (size_t)row * D_ + kt + cg * 4);
            As[cg*4+0][r] = v.x; As[cg*4+1][r] = v.y; As[cg*4+2][r] = v.z; As[cg*4+3][r] = v.w;
        }
        #pragma unroll
        for (int l = 0; l < 2; l++) {
            int f = tid + l * NTHREADS;
            int r = f >> 2, cg = f & 3;
            float4 v = *(const float4*)(W + (size_t)(n0 + r) * D_ + kt + cg * 4);
            Bs[cg*4+0][r] = v.x; Bs[cg*4+1][r] = v.y; Bs[cg*4+2][r] = v.z; Bs[cg*4+3][r] = v.w;
        }
        __syncthreads();
        #pragma unroll
        for (int k = 0; k < TK; k++) {
            float a[8], b[8];
            *(float4*)&a[0] = *(const float4*)&As[k][ty*8];
            *(float4*)&a[4] = *(const float4*)&As[k][ty*8+4];
            *(float4*)&b[0] = *(const float4*)&Bs[k][tx*8];
            *(float4*)&b[4] = *(const float4*)&Bs[k][tx*8+4];
            #pragma unroll
            for (int i = 0; i < 8; i++)
                #pragma unroll
                for (int j = 0; j < 8; j++)
                    acc[i][j] += a[i] * b[j];
        }
        __syncthreads();
    }
    const float* be = benc + e * C_;
    #pragma unroll
    for (int i = 0; i < 8; i++) {
        int pos = m0 + ty * 8 + i;
        float* dst = g_code + (size_t)pos * C_ + n0 + tx * 8;
        #pragma unroll
        for (int j = 0; j < 8; j++) {
            float v = acc[i][j] + be[n0 + tx * 8 + j];
            acc[i][j] = v > 0.f ? v : 0.f;
        }
        *(float4*)dst       = *(float4*)&acc[i][0];
        *(float4*)(dst + 4) = *(float4*)&acc[i][4];
    }
}

// ---------------------------------------------------------------------------
// Decoder GEMM + scatter + fused loss partial.
// dec[row] = code[pos] @ W_dec[e].T + b_dec[e]; partial += (dec-img)^2
// ---------------------------------------------------------------------------
__global__ void __launch_bounds__(NTHREADS) k_dec(
    const float* __restrict__ img, const float* __restrict__ Wdec,
    const float* __restrict__ bdec, float* __restrict__ dec_out, int write_dec)
{
    __shared__ float As[TK][TM];
    __shared__ float Bs[TK][TN];
    __shared__ int rows[TM];
    __shared__ float red[NTHREADS];
    int tid = threadIdx.x;
    int m0 = blockIdx.x * TM;
    int pi = blockIdx.x * NT_DEC + blockIdx.y;
    int total = g_seg[E_];
    if (m0 >= total) { if (tid == 0) g_partial[pi] = 0.f; return; }
    int e = 0;
    while (m0 >= g_seg[e + 1]) e++;
    int n0 = blockIdx.y * TN;
    const float* W = Wdec + (size_t)e * D_ * C_;
    if (tid < TM) rows[tid] = g_perm[m0 + tid];
    __syncthreads();
    int tx = tid & 15, ty = tid >> 4;
    float acc[8][8];
    #pragma unroll
    for (int i = 0; i < 8; i++)
        #pragma unroll
        for (int j = 0; j < 8; j++) acc[i][j] = 0.f;

    for (int kt = 0; kt < C_; kt += TK) {
        #pragma unroll
        for (int l = 0; l < 2; l++) {
            int f = tid + l * NTHREADS;
            int r = f >> 2, cg = f & 3;
            float4 v = *(const float4*)(g_code + (size_t)(m0 + r) * C_ + kt + cg * 4);
            As[cg*4+0][r] = v.x; As[cg*4+1][r] = v.y; As[cg*4+2][r] = v.z; As[cg*4+3][r] = v.w;
        }
        #pragma unroll
        for (int l = 0; l < 2; l++) {
            int f = tid + l * NTHREADS;
            int r = f >> 2, cg = f & 3;
            float4 v = *(const float4*)(W + (size_t)(n0 + r) * C_ + kt + cg * 4);
            Bs[cg*4+0][r] = v.x; Bs[cg*4+1][r] = v.y; Bs[cg*4+2][r] = v.z; Bs[cg*4+3][r] = v.w;
        }
        __syncthreads();
        #pragma unroll
        for (int k = 0; k < TK; k++) {
            float a[8], b[8];
            *(float4*)&a[0] = *(const float4*)&As[k][ty*8];
            *(float4*)&a[4] = *(const float4*)&As[k][ty*8+4];
            *(float4*)&b[0] = *(const float4*)&Bs[k][tx*8];
            *(float4*)&b[4] = *(const float4*)&Bs[k][tx*8+4];
            #pragma unroll
            for (int i = 0; i < 8; i++)
                #pragma unroll
                for (int j = 0; j < 8; j++)
                    acc[i][j] += a[i] * b[j];
        }
        __syncthreads();
    }

    float loss = 0.f;
    const float* bd = bdec + e * D_;
    #pragma unroll
    for (int i = 0; i < 8; i++) {
        int row = rows[ty * 8 + i];
        #pragma unroll
        for (int j = 0; j < 8; j++)
            acc[i][j] += bd[n0 + tx * 8 + j];
        if (row >= 0) {
            const float* imp = img + (size_t)row * D_ + n0 + tx * 8;
            float4 i0 = *(const float4*)imp;
            float4 i1 = *(const float4*)(imp + 4);
            float im[8] = {i0.x, i0.y, i0.z, i0.w, i1.x, i1.y, i1.z, i1.w};
            #pragma unroll
            for (int j = 0; j < 8; j++) {
                float d = acc[i][j] - im[j];
                loss += d * d;
            }
            if (write_dec) {
                float* dp = dec_out + (size_t)row * D_ + n0 + tx * 8;
                // scalar stores: dec_out may be only 4B-aligned (out+1)
                #pragma unroll
                for (int j = 0; j < 8; j++) dp[j] = acc[i][j];
            }
        }
    }
    red[tid] = loss;
    __syncthreads();
    #pragma unroll
    for (int s = NTHREADS / 2; s > 0; s >>= 1) {
        if (tid < s) red[tid] += red[tid + s];
        __syncthreads();
    }
    if (tid == 0) g_partial[pi] = red[0];
}

__global__ void k_loss(float* loss_out) {
    __shared__ float red[256];
    int tid = threadIdx.x;
    float s = 0.f;
    for (int i = tid; i < MT_MAX * NT_DEC; i += 256) s += g_partial[i];
    red[tid] = s;
    __syncthreads();
    #pragma unroll
    for (int st = 128; st > 0; st >>= 1) {
        if (tid < st) red[tid] += red[tid + st];
        __syncthreads();
    }
    if (tid == 0) *loss_out = red[0] / ((float)B_ * (float)D_);
}

// ---------------------------------------------------------------------------
extern "C" void kernel_launch(void* const* d_in, const int* in_sizes, int n_in,
                              void* d_out, int out_size) {
    const float* img  = (const float*)d_in[0];
    const void*  lab  = d_in[1];
    const float* Wenc = (const float*)d_in[2];
    const float* benc = (const float*)d_in[3];
    const float* Wdec = (const float*)d_in[4];
    const float* bdec = (const float*)d_in[5];
    float* out = (float*)d_out;
    const int BD = B_ * D_;

    float* dec_out = nullptr;
    float* loss_out = nullptr;
    int wd = 0;
    if (out_size == BD + 1)      { loss_out = out; dec_out = out + 1; wd = 1; }
    else if (out_size == BD)     { dec_out = out; wd = 1; }
    else                         { loss_out = out; }  // loss-only

    k_init<<<(B_PAD + 255) / 256, 256>>>();
    k_detect<<<(B_/2 + 255) / 256, 256>>>((const long long*)lab);
    k_route<<<1, NTHREADS>>>(lab);

    dim3 ge(MT_MAX, NT_ENC);
    k_enc<<<ge, NTHREADS>>>(img, Wenc, benc);
    dim3 gd(MT_MAX, NT_DEC);
    k_dec<<<gd, NTHREADS>>>(img, Wdec, bdec, dec_out, wd);
    if (loss_out) k_loss<<<1, 256>>>(loss_out);
}

// round 7
// speedup vs baseline: 1.7508x; 1.7508x over previous
#include <cuda_runtime.h>
#include <cuda_bf16.h>

#define B_ 8192
#define D_ 3072
#define C_ 512
#define E_ 8
#define TM 128
#define TN 128
#define BK 32
#define PAD 40            /* bf16 row stride: 80B -> conflict-free frag loads */
#define NTHREADS 256
#define MT_MAX (B_/TM + E_)       /* 72 */
#define B_PAD (MT_MAX*TM)         /* 9216 */
#define NT_DEC (D_/TN)            /* 24 */
#define NT_ENC (C_/TN)            /* 4  */

__device__ int   g_counts[E_];
__device__ int   g_seg[E_+1];
__device__ int   g_perm[B_PAD];
__device__ int   g_is64;
__device__ __nv_bfloat16 g_code_hi[(size_t)B_PAD * C_];   // 9.4 MB
__device__ __nv_bfloat16 g_code_lo[(size_t)B_PAD * C_];   // 9.4 MB
__device__ float g_partial[MT_MAX * NT_DEC];

// ---------------------------------------------------------------------------
__global__ void k_init() {
    int t = blockIdx.x * blockDim.x + threadIdx.x;
    if (t < B_PAD) g_perm[t] = -1;
    if (t == 0) g_is64 = 1;
}

__global__ void k_detect(const long long* lab) {
    int t = blockIdx.x * blockDim.x + threadIdx.x;
    if (t < B_/2) {
        long long v = lab[t];
        if (v < 0 || v >= E_) atomicExch(&g_is64, 0);
    }
}

__device__ __forceinline__ int get_label(const void* lab, int b) {
    int e;
    if (g_is64) e = (int)((const long long*)lab)[b];
    else        e = ((const int*)lab)[b];
    if (e < 0) e = 0;
    if (e >= E_) e = E_ - 1;
    return e;
}

__global__ void k_route(const void* lab) {
    __shared__ int cnt[NTHREADS][E_];
    int t = threadIdx.x;
    #pragma unroll
    for (int e = 0; e < E_; e++) cnt[t][e] = 0;
    int b0 = t * 32;
    #pragma unroll
    for (int i = 0; i < 32; i++) cnt[t][get_label(lab, b0 + i)]++;
    __syncthreads();
    if (t < E_) {
        int s = 0;
        for (int q = 0; q < NTHREADS; q++) { int c = cnt[q][t]; cnt[q][t] = s; s += c; }
        g_counts[t] = s;
    }
    __syncthreads();
    if (t == 0) {
        int s = 0;
        for (int e = 0; e < E_; e++) { g_seg[e] = s; s += ((g_counts[e] + TM - 1) / TM) * TM; }
        g_seg[E_] = s;
    }
    __syncthreads();
    int base[E_];
    #pragma unroll
    for (int e = 0; e < E_; e++) base[e] = g_seg[e] + cnt[t][e];
    #pragma unroll
    for (int i = 0; i < 32; i++) {
        int e = get_label(lab, b0 + i);
        g_perm[base[e]++] = b0 + i;
    }
}

// ---------------------------------------------------------------------------
// helpers
// ---------------------------------------------------------------------------
__device__ __forceinline__ unsigned ldsu(const __nv_bfloat16* p) {
    return *(const unsigned*)p;
}

__device__ __forceinline__ void mma16816(float* c, const unsigned* a, const unsigned* b) {
    asm volatile(
        "mma.sync.aligned.m16n8k16.row.col.f32.bf16.bf16.f32 "
        "{%0,%1,%2,%3},{%4,%5,%6,%7},{%8,%9},{%0,%1,%2,%3};\n"
        : "+f"(c[0]), "+f"(c[1]), "+f"(c[2]), "+f"(c[3])
        : "r"(a[0]), "r"(a[1]), "r"(a[2]), "r"(a[3]), "r"(b[0]), "r"(b[1]));
}

// split f32 -> bf16 hi + bf16 lo, store packed pair
__device__ __forceinline__ void split_store(__nv_bfloat16* ph, __nv_bfloat16* pl,
                                            float f0, float f1) {
    __nv_bfloat162 h, l;
    h.x = __float2bfloat16(f0);
    h.y = __float2bfloat16(f1);
    l.x = __float2bfloat16(f0 - __bfloat162float(h.x));
    l.y = __float2bfloat16(f1 - __bfloat162float(h.y));
    *(__nv_bfloat162*)ph = h;
    *(__nv_bfloat162*)pl = l;
}

// ---------------------------------------------------------------------------
// Encoder: code = relu(img[perm] @ W_enc[e].T + b_enc[e]), stored as bf16 hi/lo
// bf16x3 MMA, 128x128 tile, BK=32, 8 warps each 64x32.
// ---------------------------------------------------------------------------
__global__ void __launch_bounds__(NTHREADS) k_enc(
    const float* __restrict__ img, const float* __restrict__ Wenc,
    const float* __restrict__ benc)
{
    __shared__ alignas(16) __nv_bfloat16 Ah[TM][PAD], Al[TM][PAD];
    __shared__ alignas(16) __nv_bfloat16 Bh[TN][PAD], Bl[TN][PAD];
    __shared__ int rows[TM];
    int tid = threadIdx.x;
    int m0 = blockIdx.x * TM;
    if (m0 >= g_seg[E_]) return;
    int e = 0;
    while (m0 >= g_seg[e + 1]) e++;
    int n0 = blockIdx.y * TN;
    if (tid < TM) rows[tid] = g_perm[m0 + tid];
    __syncthreads();

    int ar = tid >> 1;            // 0..127 (row of A and of B tile)
    int ak = (tid & 1) * 16;      // k half
    int arow = rows[ar];
    const float* Ap = (arow >= 0) ? img + (size_t)arow * D_ + ak : 0;
    const float* Bp = Wenc + (size_t)e * C_ * D_ + (size_t)(n0 + ar) * D_ + ak;

    int lane = tid & 31, warp = tid >> 5;
    int mb = (warp >> 2) * 64, nb = (warp & 3) * 32;
    int lr = lane >> 2, lc = lane & 3;

    float acc[4][4][4];
    #pragma unroll
    for (int i = 0; i < 4; i++)
        #pragma unroll
        for (int j = 0; j < 4; j++)
            #pragma unroll
            for (int q = 0; q < 4; q++) acc[i][j][q] = 0.f;

    float4 aS[4], bS[4];
    #pragma unroll
    for (int ch = 0; ch < 4; ch++) {
        aS[ch] = Ap ? *(const float4*)(Ap + ch * 4) : make_float4(0.f, 0.f, 0.f, 0.f);
        bS[ch] = *(const float4*)(Bp + ch * 4);
    }

    const int NK = D_ / BK;
    for (int kt = 0; kt < NK; kt++) {
        // convert + store staged tile
        #pragma unroll
        for (int ch = 0; ch < 4; ch++) {
            int k = ak + ch * 4;
            split_store(&Ah[ar][k],     &Al[ar][k],     aS[ch].x, aS[ch].y);
            split_store(&Ah[ar][k + 2], &Al[ar][k + 2], aS[ch].z, aS[ch].w);
            split_store(&Bh[ar][k],     &Bl[ar][k],     bS[ch].x, bS[ch].y);
            split_store(&Bh[ar][k + 2], &Bl[ar][k + 2], bS[ch].z, bS[ch].w);
        }
        __syncthreads();
        // prefetch next tile (hidden behind MMAs)
        if (kt + 1 < NK) {
            #pragma unroll
            for (int ch = 0; ch < 4; ch++) {
                int k = (kt + 1) * BK + ch * 4;
                aS[ch] = Ap ? *(const float4*)(Ap + k) : make_float4(0.f, 0.f, 0.f, 0.f);
                bS[ch] = *(const float4*)(Bp + k);
            }
        }
        #pragma unroll
        for (int ks = 0; ks < 2; ks++) {
            int k = ks * 16 + lc * 2;
            unsigned ahi[4][4], alo[4][4], bhi[4][2], blo[4][2];
            #pragma unroll
            for (int mi = 0; mi < 4; mi++) {
                int r = mb + mi * 16 + lr;
                ahi[mi][0] = ldsu(&Ah[r][k]);       ahi[mi][1] = ldsu(&Ah[r + 8][k]);
                ahi[mi][2] = ldsu(&Ah[r][k + 8]);   ahi[mi][3] = ldsu(&Ah[r + 8][k + 8]);
                alo[mi][0] = ldsu(&Al[r][k]);       alo[mi][1] = ldsu(&Al[r + 8][k]);
                alo[mi][2] = ldsu(&Al[r][k + 8]);   alo[mi][3] = ldsu(&Al[r + 8][k + 8]);
            }
            #pragma unroll
            for (int ni = 0; ni < 4; ni++) {
                int n = nb + ni * 8 + lr;
                bhi[ni][0] = ldsu(&Bh[n][k]);  bhi[ni][1] = ldsu(&Bh[n][k + 8]);
                blo[ni][0] = ldsu(&Bl[n][k]);  blo[ni][1] = ldsu(&Bl[n][k + 8]);
            }
            #pragma unroll
            for (int mi = 0; mi < 4; mi++)
                #pragma unroll
                for (int ni = 0; ni < 4; ni++) {
                    mma16816(acc[mi][ni], ahi[mi], bhi[ni]);
                    mma16816(acc[mi][ni], ahi[mi], blo[ni]);
                    mma16816(acc[mi][ni], alo[mi], bhi[ni]);
                }
        }
        __syncthreads();
    }

    // epilogue: bias + relu + bf16 split store of code
    const float* be = benc + e * C_ + n0;
    #pragma unroll
    for (int mi = 0; mi < 4; mi++) {
        #pragma unroll
        for (int ni = 0; ni < 4; ni++) {
            int c = nb + ni * 8 + lc * 2;
            float b0 = be[c], b1 = be[c + 1];
            #pragma unroll
            for (int h = 0; h < 2; h++) {
                int r = mb + mi * 16 + lr + h * 8;
                size_t off = (size_t)(m0 + r) * C_ + n0 + c;
                float v0 = acc[mi][ni][h * 2 + 0] + b0; v0 = v0 > 0.f ? v0 : 0.f;
                float v1 = acc[mi][ni][h * 2 + 1] + b1; v1 = v1 > 0.f ? v1 : 0.f;
                split_store(&g_code_hi[off], &g_code_lo[off], v0, v1);
            }
        }
    }
}

// ---------------------------------------------------------------------------
// Decoder: dec = code @ W_dec[e].T + b_dec[e]; scatter + fused MSE partial.
// A already stored as bf16 hi/lo planes.
// ---------------------------------------------------------------------------
__global__ void __launch_bounds__(NTHREADS) k_dec(
    const float* __restrict__ img, const float* __restrict__ Wdec,
    const float* __restrict__ bdec, float* __restrict__ dec_out, int write_dec)
{
    __shared__ alignas(16) __nv_bfloat16 Ah[TM][PAD], Al[TM][PAD];
    __shared__ alignas(16) __nv_bfloat16 Bh[TN][PAD], Bl[TN][PAD];
    __shared__ int rows[TM];
    __shared__ float red[NTHREADS];
    int tid = threadIdx.x;
    int m0 = blockIdx.x * TM;
    int pi = blockIdx.x * NT_DEC + blockIdx.y;
    if (m0 >= g_seg[E_]) { if (tid == 0) g_partial[pi] = 0.f; return; }
    int e = 0;
    while (m0 >= g_seg[e + 1]) e++;
    int n0 = blockIdx.y * TN;
    if (tid < TM) rows[tid] = g_perm[m0 + tid];
    __syncthreads();

    int ar = tid >> 1;
    int ak = (tid & 1) * 16;
    const __nv_bfloat16* Aph = g_code_hi + (size_t)(m0 + ar) * C_ + ak;
    const __nv_bfloat16* Apl = g_code_lo + (size_t)(m0 + ar) * C_ + ak;
    const float* Bp = Wdec + (size_t)e * D_ * C_ + (size_t)(n0 + ar) * C_ + ak;

    int lane = tid & 31, warp = tid >> 5;
    int mb = (warp >> 2) * 64, nb = (warp & 3) * 32;
    int lr = lane >> 2, lc = lane & 3;

    float acc[4][4][4];
    #pragma unroll
    for (int i = 0; i < 4; i++)
        #pragma unroll
        for (int j = 0; j < 4; j++)
            #pragma unroll
            for (int q = 0; q < 4; q++) acc[i][j][q] = 0.f;

    uint4 aSh[2], aSl[2];
    float4 bS[4];
    aSh[0] = *(const uint4*)(Aph);     aSh[1] = *(const uint4*)(Aph + 8);
    aSl[0] = *(const uint4*)(Apl);     aSl[1] = *(const uint4*)(Apl + 8);
    #pragma unroll
    for (int ch = 0; ch < 4; ch++) bS[ch] = *(const float4*)(Bp + ch * 4);

    const int NK = C_ / BK;
    for (int kt = 0; kt < NK; kt++) {
        *(uint4*)&Ah[ar][ak]     = aSh[0];  *(uint4*)&Ah[ar][ak + 8] = aSh[1];
        *(uint4*)&Al[ar][ak]     = aSl[0];  *(uint4*)&Al[ar][ak + 8] = aSl[1];
        #pragma unroll
        for (int ch = 0; ch < 4; ch++) {
            int k = ak + ch * 4;
            split_store(&Bh[ar][k],     &Bl[ar][k],     bS[ch].x, bS[ch].y);
            split_store(&Bh[ar][k + 2], &Bl[ar][k + 2], bS[ch].z, bS[ch].w);
        }
        __syncthreads();
        if (kt + 1 < NK) {
            int k = (kt + 1) * BK;
            aSh[0] = *(const uint4*)(Aph + k);     aSh[1] = *(const uint4*)(Aph + k + 8);
            aSl[0] = *(const uint4*)(Apl + k);     aSl[1] = *(const uint4*)(Apl + k + 8);
            #pragma unroll
            for (int ch = 0; ch < 4; ch++) bS[ch] = *(const float4*)(Bp + k + ch * 4);
        }
        #pragma unroll
        for (int ks = 0; ks < 2; ks++) {
            int k = ks * 16 + lc * 2;
            unsigned ahi[4][4], alo[4][4], bhi[4][2], blo[4][2];
            #pragma unroll
            for (int mi = 0; mi < 4; mi++) {
                int r = mb + mi * 16 + lr;
                ahi[mi][0] = ldsu(&Ah[r][k]);       ahi[mi][1] = ldsu(&Ah[r + 8][k]);
                ahi[mi][2] = ldsu(&Ah[r][k + 8]);   ahi[mi][3] = ldsu(&Ah[r + 8][k + 8]);
                alo[mi][0] = ldsu(&Al[r][k]);       alo[mi][1] = ldsu(&Al[r + 8][k]);
                alo[mi][2] = ldsu(&Al[r][k + 8]);   alo[mi][3] = ldsu(&Al[r + 8][k + 8]);
            }
            #pragma unroll
            for (int ni = 0; ni < 4; ni++) {
                int n = nb + ni * 8 + lr;
                bhi[ni][0] = ldsu(&Bh[n][k]);  bhi[ni][1] = ldsu(&Bh[n][k + 8]);
                blo[ni][0] = ldsu(&Bl[n][k]);  blo[ni][1] = ldsu(&Bl[n][k + 8]);
            }
            #pragma unroll
            for (int mi = 0; mi < 4; mi++)
                #pragma unroll
                for (int ni = 0; ni < 4; ni++) {
                    mma16816(acc[mi][ni], ahi[mi], bhi[ni]);
                    mma16816(acc[mi][ni], ahi[mi], blo[ni]);
                    mma16816(acc[mi][ni], alo[mi], bhi[ni]);
                }
        }
        __syncthreads();
    }

    // epilogue: bias, scatter, fused squared-error partial
    float loss = 0.f;
    const float* bd = bdec + e * D_ + n0;
    #pragma unroll
    for (int mi = 0; mi < 4; mi++) {
        #pragma unroll
        for (int h = 0; h < 2; h++) {
            int r = mb + mi * 16 + lr + h * 8;
            int row = rows[r];
            #pragma unroll
            for (int ni = 0; ni < 4; ni++) {
                int c = nb + ni * 8 + lc * 2;
                float v0 = acc[mi][ni][h * 2 + 0] + bd[c];
                float v1 = acc[mi][ni][h * 2 + 1] + bd[c + 1];
                if (row >= 0) {
                    const float* ip = img + (size_t)row * D_ + n0 + c;
                    float d0 = v0 - ip[0];
                    float d1 = v1 - ip[1];
                    loss += d0 * d0 + d1 * d1;
                    if (write_dec) {
                        float* dp = dec_out + (size_t)row * D_ + n0 + c;
                        dp[0] = v0;   // scalar stores: dec_out may be out+1 (4B aligned)
                        dp[1] = v1;
                    }
                }
            }
        }
    }
    red[tid] = loss;
    __syncthreads();
    #pragma unroll
    for (int s = NTHREADS / 2; s > 0; s >>= 1) {
        if (tid < s) red[tid] += red[tid + s];
        __syncthreads();
    }
    if (tid == 0) g_partial[pi] = red[0];
}

__global__ void k_loss(float* loss_out) {
    __shared__ float red[256];
    int tid = threadIdx.x;
    float s = 0.f;
    for (int i = tid; i < MT_MAX * NT_DEC; i += 256) s += g_partial[i];
    red[tid] = s;
    __syncthreads();
    #pragma unroll
    for (int st = 128; st > 0; st >>= 1) {
        if (tid < st) red[tid] += red[tid + st];
        __syncthreads();
    }
    if (tid == 0) *loss_out = red[0] / ((float)B_ * (float)D_);
}

// ---------------------------------------------------------------------------
extern "C" void kernel_launch(void* const* d_in, const int* in_sizes, int n_in,
                              void* d_out, int out_size) {
    const float* img  = (const float*)d_in[0];
    const void*  lab  = d_in[1];
    const float* Wenc = (const float*)d_in[2];
    const float* benc = (const float*)d_in[3];
    const float* Wdec = (const float*)d_in[4];
    const float* bdec = (const float*)d_in[5];
    float* out = (float*)d_out;
    const int BD = B_ * D_;

    float* dec_out = nullptr;
    float* loss_out = nullptr;
    int wd = 0;
    if (out_size == BD + 1)      { loss_out = out; dec_out = out + 1; wd = 1; }
    else if (out_size == BD)     { dec_out = out; wd = 1; }
    else                         { loss_out = out; }

    k_init<<<(B_PAD + 255) / 256, 256>>>();
    k_detect<<<(B_/2 + 255) / 256, 256>>>((const long long*)lab);
    k_route<<<1, NTHREADS>>>(lab);

    dim3 ge(MT_MAX, NT_ENC);
    k_enc<<<ge, NTHREADS>>>(img, Wenc, benc);
    dim3 gd(MT_MAX, NT_DEC);
    k_dec<<<gd, NTHREADS>>>(img, Wdec, bdec, dec_out, wd);
    if (loss_out) k_loss<<<1, 256>>>(loss_out);
}